// round 14
// baseline (speedup 1.0000x reference)
#include <cuda_runtime.h>

#define H      128
#define VOCAB  50000
#define BATCH  128
#define TC     50
#define TI     32
#define TQ     32
#define NSEQ   (BATCH * TC)   // 6400

// ---------------- scratch (device globals; no runtime allocation) ----------------
__device__ __align__(16) float g_h   [NSEQ * H];
__device__ __align__(16) float g_gif [NSEQ * 3 * H];
__device__ __align__(16) float g_gh  [NSEQ * 3 * H];
__device__ __align__(16) float g_encf[NSEQ * H];
__device__             int   g_flen[NSEQ];
__device__             int   g_qlen[BATCH];
__device__ __align__(16) float g_giq [BATCH * TQ * 3 * H];
__device__ __align__(16) float g_hq  [BATCH * H];
__device__ __align__(16) float g_q   [BATCH * H];
__device__ __align__(16) float g_giat[NSEQ * 3 * H];
__device__ __align__(16) float g_Z   [NSEQ * 2 * H];
__device__ __align__(16) float g_P1  [NSEQ * H];
__device__ __align__(16) float g_P2  [NSEQ * H];
__device__ __align__(16) float g_W1a [H * 2 * H];
__device__ __align__(16) float g_W1b [H * 2 * H];
__device__ __align__(16) float g_mem [BATCH * H];
__device__ __align__(16) float g_e   [BATCH * H];
__device__ __align__(16) float g_yq  [BATCH * 2 * H];
__device__ __align__(16) float g_gian[BATCH * 3 * H];
__device__ __align__(16) float g_hdec[BATCH * H];

__device__ __forceinline__ float sigf(float x) { return 1.f / (1.f + expf(-x)); }

__device__ __forceinline__ float gru_comb(float ir, float iz, float in_,
                                          float hr, float hz, float hn, float h) {
    float r = sigf(ir + hr);
    float z = sigf(iz + hz);
    float n = tanhf(in_ + r * hn);
    return (1.f - z) * n + z * h;
}

// ---------------- generic GEMM: C[M,N] = A[M,K] @ W[N,K]^T + bias ----------------
// Optional row gather for A (embedding lookup): A_row(m) = emb[idx[m*idx_stride+idx_off]].
// 64x64 tile, 256 threads, 4x4 micro-tile, K chunked by 64.
__global__ void gemm_k(const float* __restrict__ A,
                       const float* __restrict__ emb,
                       const int*   __restrict__ idx, int idx_stride, int idx_off,
                       const float* __restrict__ W,
                       const float* __restrict__ bias,
                       float* __restrict__ C, long long ldc,
                       int M, int N, int K)
{
    __shared__ __align__(16) float As[64][64];
    __shared__ __align__(16) float Ws[64][64];

    int tid = threadIdx.x;
    int m0 = blockIdx.y * 64, n0 = blockIdx.x * 64;
    int row = tid & 63, seg = tid >> 6;   // seg in 0..3, 16 k-values each
    int ty = tid >> 4, tx = tid & 15;

    bool arow_ok = (m0 + row) < M;
    bool wrow_ok = (n0 + row) < N;

    const float* Arow;
    if (idx) {
        int tok = arow_ok ? idx[(m0 + row) * idx_stride + idx_off] : 0;
        Arow = emb + (long long)tok * K;
    } else {
        Arow = A + (long long)(m0 + row) * K;
    }
    const float* Wrow = W + (long long)(n0 + row) * K;

    float acc[4][4];
#pragma unroll
    for (int i = 0; i < 4; i++)
#pragma unroll
        for (int j = 0; j < 4; j++) acc[i][j] = 0.f;

    for (int kb = 0; kb < K; kb += 64) {
#pragma unroll
        for (int u = 0; u < 4; u++) {
            int k = seg * 16 + u * 4;
            float4 av = make_float4(0.f, 0.f, 0.f, 0.f);
            float4 wv = make_float4(0.f, 0.f, 0.f, 0.f);
            if (arow_ok) av = *(const float4*)(Arow + kb + k);
            if (wrow_ok) wv = *(const float4*)(Wrow + kb + k);
            As[k + 0][row] = av.x; As[k + 1][row] = av.y;
            As[k + 2][row] = av.z; As[k + 3][row] = av.w;
            Ws[k + 0][row] = wv.x; Ws[k + 1][row] = wv.y;
            Ws[k + 2][row] = wv.z; Ws[k + 3][row] = wv.w;
        }
        __syncthreads();
#pragma unroll 8
        for (int k = 0; k < 64; k++) {
            float4 a = *(const float4*)&As[k][ty * 4];
            float4 b = *(const float4*)&Ws[k][tx * 4];
            float av4[4] = {a.x, a.y, a.z, a.w};
            float bv4[4] = {b.x, b.y, b.z, b.w};
#pragma unroll
            for (int i = 0; i < 4; i++)
#pragma unroll
                for (int j = 0; j < 4; j++)
                    acc[i][j] += av4[i] * bv4[j];
        }
        __syncthreads();
    }

#pragma unroll
    for (int i = 0; i < 4; i++) {
        int m = m0 + ty * 4 + i;
        if (m >= M) continue;
#pragma unroll
        for (int j = 0; j < 4; j++) {
            int n = n0 + tx * 4 + j;
            if (n < N)
                C[(long long)m * ldc + n] = acc[i][j] + (bias ? bias[n] : 0.f);
        }
    }
}

// ---------------- elementwise GRU update for big batch (facts) ----------------
__global__ void gru_update_big(const float* __restrict__ gi, const float* __restrict__ gh,
                               float* __restrict__ h,
                               float* __restrict__ enc, const int* __restrict__ lens, int t)
{
    int i = blockIdx.x * blockDim.x + threadIdx.x;
    if (i >= NSEQ * H) return;
    int m = i >> 7, j = i & (H - 1);
    float ir = gi[m * 3 * H + j], iz = gi[m * 3 * H + H + j], in_ = gi[m * 3 * H + 2 * H + j];
    float hr = gh[m * 3 * H + j], hz = gh[m * 3 * H + H + j], hn  = gh[m * 3 * H + 2 * H + j];
    float hv = h[i];
    float hnew = gru_comb(ir, iz, in_, hr, hz, hn, hv);
    h[i] = hnew;
    if (enc && t == lens[m] - 1) enc[i] = hnew;
}

// ---------------- fused recurrent step (B=128): gh = h@Whh^T + bhh, then update ----------------
// gi precomputed (input part incl. bih); per-b row at gi + b*gstride.
__global__ void rec_step(const float* __restrict__ gi, int gstride,
                         float* __restrict__ h,
                         const float* __restrict__ Whh, const float* __restrict__ bhh,
                         float* __restrict__ enc, const int* __restrict__ lens, int t)
{
    __shared__ __align__(16) float hs[H];
    int b = blockIdx.x, j = threadIdx.x;
    hs[j] = h[b * H + j];
    __syncthreads();

    float hr = bhh[j], hz = bhh[H + j], hn = bhh[2 * H + j];
    const float4* wr = (const float4*)(Whh + j * H);
    const float4* wz = (const float4*)(Whh + (H + j) * H);
    const float4* wn = (const float4*)(Whh + (2 * H + j) * H);
    const float4* h4 = (const float4*)hs;
#pragma unroll 8
    for (int k = 0; k < H / 4; k++) {
        float4 hv = h4[k];
        float4 a = wr[k]; hr += hv.x * a.x + hv.y * a.y + hv.z * a.z + hv.w * a.w;
        float4 c = wz[k]; hz += hv.x * c.x + hv.y * c.y + hv.z * c.z + hv.w * c.w;
        float4 d = wn[k]; hn += hv.x * d.x + hv.y * d.y + hv.z * d.z + hv.w * d.w;
    }
    const float* g = gi + (long long)b * gstride;
    float hnew = gru_comb(g[j], g[H + j], g[2 * H + j], hr, hz, hn, hs[j]);
    h[b * H + j] = hnew;
    if (enc && t == lens[b] - 1) enc[b * H + j] = hnew;
}

// ---------------- episodic attention step (fused gate + attn-GRU + blend) ----------------
__global__ void ep_step(const float* __restrict__ giat,
                        const float* __restrict__ P1, const float* __restrict__ P2,
                        const float* __restrict__ W2, const float* __restrict__ b2,
                        float* __restrict__ e,
                        const float* __restrict__ Whh, const float* __restrict__ bhh,
                        int t)
{
    __shared__ __align__(16) float hs[H];
    __shared__ float red[H];
    int b = blockIdx.x, j = threadIdx.x;
    int s = b * TC + t;

    hs[j] = e[b * H + j];
    float u = tanhf(P1[s * H + j] + P2[s * H + j]);
    red[j] = u * W2[j];
    __syncthreads();
    for (int off = H / 2; off > 0; off >>= 1) {
        if (j < off) red[j] += red[j + off];
        __syncthreads();
    }
    float gate = sigf(red[0] + b2[0]);

    float hr = bhh[j], hz = bhh[H + j], hn = bhh[2 * H + j];
    const float4* wr = (const float4*)(Whh + j * H);
    const float4* wz = (const float4*)(Whh + (H + j) * H);
    const float4* wn = (const float4*)(Whh + (2 * H + j) * H);
    const float4* h4 = (const float4*)hs;
#pragma unroll 8
    for (int k = 0; k < H / 4; k++) {
        float4 hv = h4[k];
        float4 a = wr[k]; hr += hv.x * a.x + hv.y * a.y + hv.z * a.z + hv.w * a.w;
        float4 c = wz[k]; hz += hv.x * c.x + hv.y * c.y + hv.z * c.z + hv.w * c.w;
        float4 d = wn[k]; hn += hv.x * d.x + hv.y * d.y + hv.z * d.z + hv.w * d.w;
    }
    const float* gi = giat + (long long)s * 3 * H;
    float h2 = gru_comb(gi[j], gi[H + j], gi[2 * H + j], hr, hz, hn, hs[j]);
    e[b * H + j] = gate * h2 + (1.f - gate) * hs[j];
}

// ---------------- full GRU cell for B=128 (memory update) ----------------
__global__ void gru_full(const float* __restrict__ x, const float* __restrict__ h_in,
                         float* __restrict__ h_out,
                         const float* __restrict__ Wih, const float* __restrict__ Whh,
                         const float* __restrict__ bih, const float* __restrict__ bhh,
                         int IN)
{
    __shared__ __align__(16) float xs[2 * H];
    __shared__ __align__(16) float hs[H];
    int b = blockIdx.x, j = threadIdx.x;
    hs[j] = h_in[b * H + j];
    for (int k = j; k < IN; k += H) xs[k] = x[b * IN + k];
    __syncthreads();

    float ir = bih[j], iz = bih[H + j], in_ = bih[2 * H + j];
    const float4* xr = (const float4*)(Wih + (long long)j * IN);
    const float4* xz = (const float4*)(Wih + (long long)(H + j) * IN);
    const float4* xn = (const float4*)(Wih + (long long)(2 * H + j) * IN);
    const float4* x4 = (const float4*)xs;
    for (int k = 0; k < IN / 4; k++) {
        float4 xv = x4[k];
        float4 a = xr[k]; ir += xv.x * a.x + xv.y * a.y + xv.z * a.z + xv.w * a.w;
        float4 c = xz[k]; iz += xv.x * c.x + xv.y * c.y + xv.z * c.z + xv.w * c.w;
        float4 d = xn[k]; in_ += xv.x * d.x + xv.y * d.y + xv.z * d.z + xv.w * d.w;
    }
    float hr = bhh[j], hz = bhh[H + j], hn = bhh[2 * H + j];
    const float4* wr = (const float4*)(Whh + j * H);
    const float4* wz = (const float4*)(Whh + (H + j) * H);
    const float4* wn = (const float4*)(Whh + (2 * H + j) * H);
    const float4* h4 = (const float4*)hs;
#pragma unroll 8
    for (int k = 0; k < H / 4; k++) {
        float4 hv = h4[k];
        float4 a = wr[k]; hr += hv.x * a.x + hv.y * a.y + hv.z * a.z + hv.w * a.w;
        float4 c = wz[k]; hz += hv.x * c.x + hv.y * c.y + hv.z * c.z + hv.w * c.w;
        float4 d = wn[k]; hn += hv.x * d.x + hv.y * d.y + hv.z * d.z + hv.w * d.w;
    }
    h_out[b * H + j] = gru_comb(ir, iz, in_, hr, hz, hn, hs[j]);
}

// ---------------- misc small kernels ----------------
__global__ void count_len(const int* __restrict__ masks, int* __restrict__ lens, int n, int T)
{
    int i = blockIdx.x * blockDim.x + threadIdx.x;
    if (i < n) {
        int c = 0;
        for (int t = 0; t < T; t++) c += (masks[i * T + t] == 0);
        lens[i] = c;
    }
}

__global__ void build_z(const float* __restrict__ encf, const float* __restrict__ vec,
                        float* __restrict__ Z)
{
    int i = blockIdx.x * blockDim.x + threadIdx.x;
    if (i >= NSEQ * 2 * H) return;
    int s = i >> 8, k = i & (2 * H - 1);
    int b = s / TC;
    int kk = k & (H - 1);
    float f = encf[s * H + kk], v = vec[b * H + kk];
    Z[i] = (k < H) ? f * v : fabsf(f - v);
}

// gate_W1 is (H, 4H); cols: [f*q | f*m | |f-q| | |f-m|]. Pack q-part and m-part.
__global__ void pack_w1(const float* __restrict__ W1, float* __restrict__ Wa,
                        float* __restrict__ Wb)
{
    int i = blockIdx.x * blockDim.x + threadIdx.x;
    if (i >= H * 2 * H) return;
    int j = i >> 8, k = i & (2 * H - 1);
    int ca = (k < H) ? k : (k + H);          // cols 0:H and 2H:3H
    int cb = (k < H) ? (k + H) : (k + 2 * H); // cols H:2H and 3H:4H
    Wa[i] = W1[j * 4 * H + ca];
    Wb[i] = W1[j * 4 * H + cb];
}

__global__ void build_yq(const float* __restrict__ embed, const float* __restrict__ q,
                         float* __restrict__ yq)
{
    int i = blockIdx.x * blockDim.x + threadIdx.x;
    if (i >= BATCH * 2 * H) return;
    int b = i >> 8, k = i & (2 * H - 1);
    yq[i] = (k < H) ? embed[2 * H + k] : q[b * H + (k - H)];
}

// in-place log_softmax over one vocab row per block
__global__ void lsm(float* __restrict__ base, long long rowstride)
{
    float* row = base + (long long)blockIdx.x * rowstride;
    __shared__ float red[256];
    int tid = threadIdx.x;
    float mx = -1e30f;
    for (int i = tid; i < VOCAB; i += 256) mx = fmaxf(mx, row[i]);
    red[tid] = mx; __syncthreads();
    for (int o = 128; o > 0; o >>= 1) {
        if (tid < o) red[tid] = fmaxf(red[tid], red[tid + o]);
        __syncthreads();
    }
    mx = red[0]; __syncthreads();
    float s = 0.f;
    for (int i = tid; i < VOCAB; i += 256) s += expf(row[i] - mx);
    red[tid] = s; __syncthreads();
    for (int o = 128; o > 0; o >>= 1) {
        if (tid < o) red[tid] += red[tid + o];
        __syncthreads();
    }
    float lse = mx + logf(red[0]);
    for (int i = tid; i < VOCAB; i += 256) row[i] -= lse;
}

// ---------------- host side ----------------
static void* sym_addr(const void* s) { void* p = nullptr; cudaGetSymbolAddress(&p, s); return p; }

static void gemm(const float* A, const float* emb, const int* idx, int idx_stride, int idx_off,
                 const float* W, const float* bias, float* C, long long ldc,
                 int M, int N, int K)
{
    dim3 grid((N + 63) / 64, (M + 63) / 64);
    gemm_k<<<grid, 256>>>(A, emb, idx, idx_stride, idx_off, W, bias, C, ldc, M, N, K);
}

extern "C" void kernel_launch(void* const* d_in, const int* in_sizes, int n_in,
                              void* d_out, int out_size)
{
    const int* facts = (const int*)d_in[0];
    const int* fmask = (const int*)d_in[1];
    const int* ques  = (const int*)d_in[2];
    const int* qmask = (const int*)d_in[3];
    int ai = 4;
    if (in_sizes[4] == 1) ai = 5;   // skip num_decode scalar if present
    const float* embed   = (const float*)d_in[ai++];
    const float* ig_Wih  = (const float*)d_in[ai++];
    const float* ig_Whh  = (const float*)d_in[ai++];
    const float* ig_bih  = (const float*)d_in[ai++];
    const float* ig_bhh  = (const float*)d_in[ai++];
    const float* qg_Wih  = (const float*)d_in[ai++];
    const float* qg_Whh  = (const float*)d_in[ai++];
    const float* qg_bih  = (const float*)d_in[ai++];
    const float* qg_bhh  = (const float*)d_in[ai++];
    const float* at_Wih  = (const float*)d_in[ai++];
    const float* at_Whh  = (const float*)d_in[ai++];
    const float* at_bih  = (const float*)d_in[ai++];
    const float* at_bhh  = (const float*)d_in[ai++];
    const float* me_Wih  = (const float*)d_in[ai++];
    const float* me_Whh  = (const float*)d_in[ai++];
    const float* me_bih  = (const float*)d_in[ai++];
    const float* me_bhh  = (const float*)d_in[ai++];
    const float* an_Wih  = (const float*)d_in[ai++];
    const float* an_Whh  = (const float*)d_in[ai++];
    const float* an_bih  = (const float*)d_in[ai++];
    const float* an_bhh  = (const float*)d_in[ai++];
    const float* gate_W1 = (const float*)d_in[ai++];
    const float* gate_b1 = (const float*)d_in[ai++];
    const float* gate_W2 = (const float*)d_in[ai++];
    const float* gate_b2 = (const float*)d_in[ai++];
    const float* fc_W    = (const float*)d_in[ai++];
    const float* fc_b    = (const float*)d_in[ai++];
    float* out = (float*)d_out;
    int TD = out_size / (BATCH * VOCAB);
    if (TD <= 0) TD = 8;

    float* h    = (float*)sym_addr(g_h);
    float* gif  = (float*)sym_addr(g_gif);
    float* gh   = (float*)sym_addr(g_gh);
    float* encf = (float*)sym_addr(g_encf);
    int*   flen = (int*)  sym_addr(g_flen);
    int*   qlen = (int*)  sym_addr(g_qlen);
    float* giq  = (float*)sym_addr(g_giq);
    float* hq   = (float*)sym_addr(g_hq);
    float* q    = (float*)sym_addr(g_q);
    float* giat = (float*)sym_addr(g_giat);
    float* Z    = (float*)sym_addr(g_Z);
    float* P1   = (float*)sym_addr(g_P1);
    float* P2   = (float*)sym_addr(g_P2);
    float* W1a  = (float*)sym_addr(g_W1a);
    float* W1b  = (float*)sym_addr(g_W1b);
    float* mem  = (float*)sym_addr(g_mem);
    float* e    = (float*)sym_addr(g_e);
    float* yq   = (float*)sym_addr(g_yq);
    float* gian = (float*)sym_addr(g_gian);
    float* hdec = (float*)sym_addr(g_hdec);

    // ---- sequence lengths from masks ----
    count_len<<<(NSEQ + 255) / 256, 256>>>(fmask, flen, NSEQ, TI);
    count_len<<<1, 128>>>(qmask, qlen, BATCH, TQ);

    // ---- fact encoder: batched GRU over 6400 sequences x 32 steps ----
    cudaMemsetAsync(h, 0, (size_t)NSEQ * H * sizeof(float));
    for (int t = 0; t < TI; t++) {
        gemm(nullptr, embed, facts, TI, t, ig_Wih, ig_bih, gif, 3 * H, NSEQ, 3 * H, H);
        gemm(h, nullptr, nullptr, 0, 0, ig_Whh, ig_bhh, gh, 3 * H, NSEQ, 3 * H, H);
        gru_update_big<<<NSEQ * H / 256, 256>>>(gif, gh, h, encf, flen, t);
    }

    // ---- question encoder ----
    cudaMemsetAsync(hq, 0, (size_t)BATCH * H * sizeof(float));
    gemm(nullptr, embed, ques, 1, 0, qg_Wih, qg_bih, giq, 3 * H, BATCH * TQ, 3 * H, H);
    for (int t = 0; t < TQ; t++)
        rec_step<<<BATCH, H>>>(giq + (long long)t * 3 * H, TQ * 3 * H, hq,
                               qg_Whh, qg_bhh, q, qlen, t);

    // ---- episodic memory ----
    pack_w1<<<(H * 2 * H) / 256, 256>>>(gate_W1, W1a, W1b);
    gemm(encf, nullptr, nullptr, 0, 0, at_Wih, at_bih, giat, 3 * H, NSEQ, 3 * H, H);
    build_z<<<(NSEQ * 2 * H) / 256, 256>>>(encf, q, Z);
    gemm(Z, nullptr, nullptr, 0, 0, W1a, gate_b1, P1, H, NSEQ, H, 2 * H);
    cudaMemcpyAsync(mem, q, (size_t)BATCH * H * sizeof(float), cudaMemcpyDeviceToDevice);

    for (int ep = 0; ep < 3; ep++) {
        build_z<<<(NSEQ * 2 * H) / 256, 256>>>(encf, mem, Z);
        gemm(Z, nullptr, nullptr, 0, 0, W1b, nullptr, P2, H, NSEQ, H, 2 * H);
        cudaMemsetAsync(e, 0, (size_t)BATCH * H * sizeof(float));
        for (int t = 0; t < TC; t++)
            ep_step<<<BATCH, H>>>(giat, P1, P2, gate_W2, gate_b2, e, at_Whh, at_bhh, t);
        gru_full<<<BATCH, H>>>(e, mem, mem, me_Wih, me_Whh, me_bih, me_bhh, H);
    }

    // ---- answer decoder ----
    build_yq<<<(BATCH * 2 * H) / 256, 256>>>(embed, q, yq);
    gemm(yq, nullptr, nullptr, 0, 0, an_Wih, an_bih, gian, 3 * H, BATCH, 3 * H, 2 * H);
    cudaMemcpyAsync(hdec, mem, (size_t)BATCH * H * sizeof(float), cudaMemcpyDeviceToDevice);
    for (int t = 0; t < TD; t++) {
        rec_step<<<BATCH, H>>>(gian, 3 * H, hdec, an_Whh, an_bhh, nullptr, nullptr, 0);
        gemm(hdec, nullptr, nullptr, 0, 0, fc_W, fc_b,
             out + (long long)t * VOCAB, (long long)TD * VOCAB, BATCH, VOCAB, H);
        lsm<<<BATCH, 256>>>(out + (long long)t * VOCAB, (long long)TD * VOCAB);
    }
}

// round 15
// speedup vs baseline: 1.9205x; 1.9205x over previous
#include <cuda_runtime.h>

#define H      128
#define VOCAB  50000
#define BATCH  128
#define TC     50
#define TI     32
#define TQ     32
#define NSEQ   (BATCH * TC)   // 6400

// ---------------- scratch (device globals) ----------------
__device__ __align__(16) float g_embW[VOCAB * 3 * H];   // embed @ ig_Wih^T + ig_bih
__device__ __align__(16) float g_h   [NSEQ * H];
__device__ __align__(16) float g_encf[NSEQ * H];
__device__             int   g_flen[NSEQ];
__device__             int   g_qlen[BATCH];
__device__ __align__(16) float g_giq [BATCH * TQ * 3 * H];
__device__ __align__(16) float g_q   [BATCH * H];
__device__ __align__(16) float g_giat[NSEQ * 3 * H];
__device__ __align__(16) float g_Z   [NSEQ * 2 * H];
__device__ __align__(16) float g_P1  [NSEQ * H];
__device__ __align__(16) float g_P2  [NSEQ * H];
__device__ __align__(16) float g_W1a [H * 2 * H];
__device__ __align__(16) float g_W1b [H * 2 * H];
__device__ __align__(16) float g_mem [BATCH * H];
__device__ __align__(16) float g_e   [BATCH * H];
__device__ __align__(16) float g_yq  [BATCH * 2 * H];
__device__ __align__(16) float g_gian[BATCH * 3 * H];
__device__ __align__(16) float g_hdec[BATCH * H];

__device__ __forceinline__ float sigf(float x) { return 1.f / (1.f + expf(-x)); }

__device__ __forceinline__ float gru_comb(float ir, float iz, float in_,
                                          float hr, float hz, float hn, float h) {
    float r = sigf(ir + hr);
    float z = sigf(iz + hz);
    float n = tanhf(in_ + r * hn);
    return (1.f - z) * n + z * h;
}

__device__ __forceinline__ unsigned f2tf32(float f) {
    unsigned r; asm("cvt.rna.tf32.f32 %0, %1;" : "=r"(r) : "f"(f)); return r;
}

__device__ __forceinline__ void mma8(float* c, const unsigned* a, const unsigned* b) {
    asm volatile("mma.sync.aligned.m16n8k8.row.col.f32.tf32.tf32.f32 "
                 "{%0,%1,%2,%3}, {%4,%5,%6,%7}, {%8,%9}, {%0,%1,%2,%3};"
                 : "+f"(c[0]), "+f"(c[1]), "+f"(c[2]), "+f"(c[3])
                 : "r"(a[0]), "r"(a[1]), "r"(a[2]), "r"(a[3]), "r"(b[0]), "r"(b[1]));
}

// ---------------- generic tf32 tensor GEMM: C[M,N] = A[M,K] @ W[N,K]^T + bias ----------
// Tile: BM=64, BN=128, BK=32. 256 threads, 8 warps (2x4), warp tile 32x32.
// Optional row gather: A_row(m) = emb[idx[m*idx_stride + idx_off]].
__global__ __launch_bounds__(256) void tmma_gemm(
    const float* __restrict__ A, const float* __restrict__ emb,
    const int* __restrict__ idx, int idx_stride, int idx_off,
    const float* __restrict__ W, const float* __restrict__ bias,
    float* __restrict__ C, long long ldc, int M, int N, int K)
{
    __shared__ unsigned As[64 * 36];
    __shared__ unsigned Ws[128 * 36];
    int tid = threadIdx.x, lane = tid & 31, wid = tid >> 5;
    int wm = wid & 1, wn = wid >> 1;
    int g = lane >> 2, qd = lane & 3;
    int m0 = blockIdx.y * 64, n0 = blockIdx.x * 128;

    int ar = tid >> 2, ac = (tid & 3) * 8;
    bool a_ok = (m0 + ar) < M;
    const float* Arow;
    if (idx) {
        int tok = a_ok ? idx[(m0 + ar) * idx_stride + idx_off] : 0;
        Arow = emb + (long long)tok * K;
    } else {
        Arow = A + (long long)(m0 + ar) * K;
    }

    float c[2][4][4] = {};

    for (int kc = 0; kc < K; kc += 32) {
        {
            float4 v0 = a_ok ? *(const float4*)(Arow + kc + ac) : make_float4(0, 0, 0, 0);
            float4 v1 = a_ok ? *(const float4*)(Arow + kc + ac + 4) : make_float4(0, 0, 0, 0);
            unsigned* d = &As[ar * 36 + ac];
            d[0] = f2tf32(v0.x); d[1] = f2tf32(v0.y); d[2] = f2tf32(v0.z); d[3] = f2tf32(v0.w);
            d[4] = f2tf32(v1.x); d[5] = f2tf32(v1.y); d[6] = f2tf32(v1.z); d[7] = f2tf32(v1.w);
        }
        for (int i = tid; i < 1024; i += 256) {
            int r = i >> 3, cc = (i & 7) * 4;
            bool ok = (n0 + r) < N;
            float4 v = ok ? *(const float4*)(W + (long long)(n0 + r) * K + kc + cc)
                          : make_float4(0, 0, 0, 0);
            unsigned* d = &Ws[r * 36 + cc];
            d[0] = f2tf32(v.x); d[1] = f2tf32(v.y); d[2] = f2tf32(v.z); d[3] = f2tf32(v.w);
        }
        __syncthreads();
#pragma unroll
        for (int ks = 0; ks < 4; ks++) {
            int k = ks * 8;
            unsigned a[2][4], b[4][2];
#pragma unroll
            for (int mf = 0; mf < 2; mf++) {
                int rb = wm * 32 + mf * 16 + g;
                a[mf][0] = As[rb * 36 + k + qd];
                a[mf][1] = As[(rb + 8) * 36 + k + qd];
                a[mf][2] = As[rb * 36 + k + qd + 4];
                a[mf][3] = As[(rb + 8) * 36 + k + qd + 4];
            }
#pragma unroll
            for (int nf = 0; nf < 4; nf++) {
                int nb = wn * 32 + nf * 8 + g;
                b[nf][0] = Ws[nb * 36 + k + qd];
                b[nf][1] = Ws[nb * 36 + k + qd + 4];
            }
#pragma unroll
            for (int mf = 0; mf < 2; mf++)
#pragma unroll
                for (int nf = 0; nf < 4; nf++)
                    mma8(c[mf][nf], a[mf], b[nf]);
        }
        __syncthreads();
    }

#pragma unroll
    for (int mf = 0; mf < 2; mf++) {
#pragma unroll
        for (int nf = 0; nf < 4; nf++) {
            int row = m0 + wm * 32 + mf * 16 + g;
            int col = n0 + wn * 32 + nf * 8 + 2 * qd;
            float b0 = 0.f, b1 = 0.f;
            if (bias) { if (col < N) b0 = bias[col]; if (col + 1 < N) b1 = bias[col + 1]; }
            if (row < M) {
                if (col < N)     C[(long long)row * ldc + col]     = c[mf][nf][0] + b0;
                if (col + 1 < N) C[(long long)row * ldc + col + 1] = c[mf][nf][1] + b1;
            }
            if (row + 8 < M) {
                if (col < N)     C[(long long)(row + 8) * ldc + col]     = c[mf][nf][2] + b0;
                if (col + 1 < N) C[(long long)(row + 8) * ldc + col + 1] = c[mf][nf][3] + b1;
            }
        }
    }
}

// ---------------- fused fact-GRU step: gh = h@Whh^T (tensor), gi gathered from embW,
// full GRU combine + h update + enc capture. BM=64, BN=384 (all gates in-block).
__global__ __launch_bounds__(256) void tmma_gru_step(
    float* __restrict__ h, const float* __restrict__ Whh, const float* __restrict__ bhh,
    const float* __restrict__ embW, const int* __restrict__ facts,
    const int* __restrict__ lens, float* __restrict__ enc, int t)
{
    extern __shared__ unsigned sm[];
    unsigned* As = sm;               // 64 x 36
    unsigned* Ws = sm + 64 * 36;     // 384 x 36
    float* ghs = (float*)sm;         // 64 x 388 (reused after mma phase)

    int tid = threadIdx.x, lane = tid & 31, wid = tid >> 5;
    int wm = wid & 1, wn = wid >> 1;   // warp tile 32 (M) x 96 (N)
    int g = lane >> 2, qd = lane & 3;
    int m0 = blockIdx.x * 64;

    int ar = tid >> 2, ac = (tid & 3) * 8;
    const float* Arow = h + (long long)(m0 + ar) * H;

    float c[2][12][4] = {};

    for (int kc = 0; kc < H; kc += 32) {
        {
            float4 v0 = *(const float4*)(Arow + kc + ac);
            float4 v1 = *(const float4*)(Arow + kc + ac + 4);
            unsigned* d = &As[ar * 36 + ac];
            d[0] = f2tf32(v0.x); d[1] = f2tf32(v0.y); d[2] = f2tf32(v0.z); d[3] = f2tf32(v0.w);
            d[4] = f2tf32(v1.x); d[5] = f2tf32(v1.y); d[6] = f2tf32(v1.z); d[7] = f2tf32(v1.w);
        }
        for (int i = tid; i < 3072; i += 256) {   // 384 rows x 8 float4
            int r = i >> 3, cc = (i & 7) * 4;
            float4 v = *(const float4*)(Whh + (long long)r * H + kc + cc);
            unsigned* d = &Ws[r * 36 + cc];
            d[0] = f2tf32(v.x); d[1] = f2tf32(v.y); d[2] = f2tf32(v.z); d[3] = f2tf32(v.w);
        }
        __syncthreads();
#pragma unroll
        for (int ks = 0; ks < 4; ks++) {
            int k = ks * 8;
            unsigned a[2][4];
#pragma unroll
            for (int mf = 0; mf < 2; mf++) {
                int rb = wm * 32 + mf * 16 + g;
                a[mf][0] = As[rb * 36 + k + qd];
                a[mf][1] = As[(rb + 8) * 36 + k + qd];
                a[mf][2] = As[rb * 36 + k + qd + 4];
                a[mf][3] = As[(rb + 8) * 36 + k + qd + 4];
            }
#pragma unroll
            for (int nf = 0; nf < 12; nf++) {
                int nb = wn * 96 + nf * 8 + g;
                unsigned b[2];
                b[0] = Ws[nb * 36 + k + qd];
                b[1] = Ws[nb * 36 + k + qd + 4];
                mma8(c[0][nf], a[0], b);
                mma8(c[1][nf], a[1], b);
            }
        }
        __syncthreads();
    }

    // stash accumulators to smem (64 x 384, stride 388)
#pragma unroll
    for (int mf = 0; mf < 2; mf++) {
#pragma unroll
        for (int nf = 0; nf < 12; nf++) {
            int row = wm * 32 + mf * 16 + g;
            int col = wn * 96 + nf * 8 + 2 * qd;
            ghs[row * 388 + col]           = c[mf][nf][0];
            ghs[row * 388 + col + 1]       = c[mf][nf][1];
            ghs[(row + 8) * 388 + col]     = c[mf][nf][2];
            ghs[(row + 8) * 388 + col + 1] = c[mf][nf][3];
        }
    }
    __syncthreads();

    // GRU combine
    for (int e = tid; e < 64 * H; e += 256) {
        int m = e >> 7, j = e & (H - 1);
        int sq = m0 + m;
        float hr = ghs[m * 388 + j]           + bhh[j];
        float hz = ghs[m * 388 + H + j]       + bhh[H + j];
        float hn = ghs[m * 388 + 2 * H + j]   + bhh[2 * H + j];
        int tok = facts[sq * TI + t];
        const float* gi = embW + (long long)tok * (3 * H);
        float hold = h[sq * H + j];
        float hnew = gru_comb(gi[j], gi[H + j], gi[2 * H + j], hr, hz, hn, hold);
        h[sq * H + j] = hnew;
        if (t == lens[sq] - 1) enc[sq * H + j] = hnew;
    }
}

// ---------------- fused question encoder: one block per batch elem, 32 steps ----------
__global__ __launch_bounds__(128) void q_encode(
    const float* __restrict__ gi_all, const float* __restrict__ Whh,
    const float* __restrict__ bhh, const int* __restrict__ qlen,
    float* __restrict__ q)
{
    extern __shared__ float WsT[];   // [k*385 + n], k<128, n<384
    __shared__ float hs[H];
    int b = blockIdx.x, j = threadIdx.x;
    for (int s = j; s < 3 * H * H; s += H) {
        int n = s >> 7, k = s & (H - 1);
        WsT[k * 385 + n] = Whh[s];
    }
    float br = bhh[j], bz = bhh[H + j], bn = bhh[2 * H + j];
    hs[j] = 0.f;
    __syncthreads();
    int L = qlen[b];
    for (int t = 0; t < TQ; t++) {
        float hr = br, hz = bz, hn = bn;
#pragma unroll 4
        for (int k = 0; k < H; k++) {
            float hv = hs[k];
            hr += WsT[k * 385 + j] * hv;
            hz += WsT[k * 385 + H + j] * hv;
            hn += WsT[k * 385 + 2 * H + j] * hv;
        }
        const float* gi = gi_all + (long long)(b * TQ + t) * (3 * H);
        float hnew = gru_comb(gi[j], gi[H + j], gi[2 * H + j], hr, hz, hn, hs[j]);
        __syncthreads();
        hs[j] = hnew;
        __syncthreads();
        if (t == L - 1) q[b * H + j] = hnew;
    }
}

// ---------------- fused episode: one block per batch elem, all 50 attn steps ----------
__global__ __launch_bounds__(128) void ep_fused(
    const float* __restrict__ giat, const float* __restrict__ P1,
    const float* __restrict__ P2, const float* __restrict__ W2,
    const float* __restrict__ b2, const float* __restrict__ Whh,
    const float* __restrict__ bhh, float* __restrict__ e_out)
{
    extern __shared__ float WsT[];
    __shared__ float hs[H];
    __shared__ float wsum[4];
    int b = blockIdx.x, j = threadIdx.x;
    int lane = j & 31, wrp = j >> 5;
    for (int s = j; s < 3 * H * H; s += H) {
        int n = s >> 7, k = s & (H - 1);
        WsT[k * 385 + n] = Whh[s];
    }
    float br = bhh[j], bz = bhh[H + j], bn = bhh[2 * H + j];
    float w2j = W2[j], b2v = b2[0];
    hs[j] = 0.f;
    float en = 0.f;
    __syncthreads();
    for (int t = 0; t < TC; t++) {
        long long s = (long long)(b * TC + t);
        float u = tanhf(P1[s * H + j] + P2[s * H + j]) * w2j;
        for (int o = 16; o; o >>= 1) u += __shfl_down_sync(0xffffffffu, u, o);
        if (lane == 0) wsum[wrp] = u;
        float hr = br, hz = bz, hn = bn;
#pragma unroll 4
        for (int k = 0; k < H; k++) {
            float hv = hs[k];
            hr += WsT[k * 385 + j] * hv;
            hz += WsT[k * 385 + H + j] * hv;
            hn += WsT[k * 385 + 2 * H + j] * hv;
        }
        __syncthreads();
        float gate = sigf(wsum[0] + wsum[1] + wsum[2] + wsum[3] + b2v);
        const float* gi = giat + s * (3 * H);
        float h2 = gru_comb(gi[j], gi[H + j], gi[2 * H + j], hr, hz, hn, hs[j]);
        en = gate * h2 + (1.f - gate) * hs[j];
        __syncthreads();
        hs[j] = en;
        __syncthreads();
    }
    e_out[b * H + j] = en;
}

// ---------------- decoder recurrent step (B=128), exact fp32 ----------------
__global__ void rec_step(const float* __restrict__ gi, int gstride,
                         float* __restrict__ h,
                         const float* __restrict__ Whh, const float* __restrict__ bhh)
{
    __shared__ __align__(16) float hs[H];
    int b = blockIdx.x, j = threadIdx.x;
    hs[j] = h[b * H + j];
    __syncthreads();
    float hr = bhh[j], hz = bhh[H + j], hn = bhh[2 * H + j];
    const float4* wr = (const float4*)(Whh + j * H);
    const float4* wz = (const float4*)(Whh + (H + j) * H);
    const float4* wn = (const float4*)(Whh + (2 * H + j) * H);
    const float4* h4 = (const float4*)hs;
#pragma unroll 8
    for (int k = 0; k < H / 4; k++) {
        float4 hv = h4[k];
        float4 a = wr[k]; hr += hv.x * a.x + hv.y * a.y + hv.z * a.z + hv.w * a.w;
        float4 c = wz[k]; hz += hv.x * c.x + hv.y * c.y + hv.z * c.z + hv.w * c.w;
        float4 d = wn[k]; hn += hv.x * d.x + hv.y * d.y + hv.z * d.z + hv.w * d.w;
    }
    const float* g = gi + (long long)b * gstride;
    h[b * H + j] = gru_comb(g[j], g[H + j], g[2 * H + j], hr, hz, hn, hs[j]);
}

// ---------------- memory-update GRU (B=128), exact fp32 ----------------
__global__ void gru_full(const float* __restrict__ x, const float* __restrict__ h_in,
                         float* __restrict__ h_out,
                         const float* __restrict__ Wih, const float* __restrict__ Whh,
                         const float* __restrict__ bih, const float* __restrict__ bhh,
                         int IN)
{
    __shared__ __align__(16) float xs[2 * H];
    __shared__ __align__(16) float hs[H];
    int b = blockIdx.x, j = threadIdx.x;
    hs[j] = h_in[b * H + j];
    for (int k = j; k < IN; k += H) xs[k] = x[b * IN + k];
    __syncthreads();
    float ir = bih[j], iz = bih[H + j], in_ = bih[2 * H + j];
    const float4* xr = (const float4*)(Wih + (long long)j * IN);
    const float4* xz = (const float4*)(Wih + (long long)(H + j) * IN);
    const float4* xn = (const float4*)(Wih + (long long)(2 * H + j) * IN);
    const float4* x4 = (const float4*)xs;
    for (int k = 0; k < IN / 4; k++) {
        float4 xv = x4[k];
        float4 a = xr[k]; ir += xv.x * a.x + xv.y * a.y + xv.z * a.z + xv.w * a.w;
        float4 c = xz[k]; iz += xv.x * c.x + xv.y * c.y + xv.z * c.z + xv.w * c.w;
        float4 d = xn[k]; in_ += xv.x * d.x + xv.y * d.y + xv.z * d.z + xv.w * d.w;
    }
    float hr = bhh[j], hz = bhh[H + j], hn = bhh[2 * H + j];
    const float4* wr = (const float4*)(Whh + j * H);
    const float4* wz = (const float4*)(Whh + (H + j) * H);
    const float4* wn = (const float4*)(Whh + (2 * H + j) * H);
    const float4* h4 = (const float4*)hs;
#pragma unroll 8
    for (int k = 0; k < H / 4; k++) {
        float4 hv = h4[k];
        float4 a = wr[k]; hr += hv.x * a.x + hv.y * a.y + hv.z * a.z + hv.w * a.w;
        float4 c = wz[k]; hz += hv.x * c.x + hv.y * c.y + hv.z * c.z + hv.w * c.w;
        float4 d = wn[k]; hn += hv.x * d.x + hv.y * d.y + hv.z * d.z + hv.w * d.w;
    }
    h_out[b * H + j] = gru_comb(ir, iz, in_, hr, hz, hn, hs[j]);
}

// ---------------- misc small kernels ----------------
__global__ void count_len(const int* __restrict__ masks, int* __restrict__ lens, int n, int T)
{
    int i = blockIdx.x * blockDim.x + threadIdx.x;
    if (i < n) {
        int c = 0;
        for (int t = 0; t < T; t++) c += (masks[i * T + t] == 0);
        lens[i] = c;
    }
}

__global__ void build_z(const float* __restrict__ encf, const float* __restrict__ vec,
                        float* __restrict__ Z)
{
    int i = blockIdx.x * blockDim.x + threadIdx.x;
    if (i >= NSEQ * 2 * H) return;
    int s = i >> 8, k = i & (2 * H - 1);
    int b = s / TC;
    int kk = k & (H - 1);
    float f = encf[s * H + kk], v = vec[b * H + kk];
    Z[i] = (k < H) ? f * v : fabsf(f - v);
}

__global__ void pack_w1(const float* __restrict__ W1, float* __restrict__ Wa,
                        float* __restrict__ Wb)
{
    int i = blockIdx.x * blockDim.x + threadIdx.x;
    if (i >= H * 2 * H) return;
    int j = i >> 8, k = i & (2 * H - 1);
    int ca = (k < H) ? k : (k + H);
    int cb = (k < H) ? (k + H) : (k + 2 * H);
    Wa[i] = W1[j * 4 * H + ca];
    Wb[i] = W1[j * 4 * H + cb];
}

__global__ void build_yq(const float* __restrict__ embed, const float* __restrict__ q,
                         float* __restrict__ yq)
{
    int i = blockIdx.x * blockDim.x + threadIdx.x;
    if (i >= BATCH * 2 * H) return;
    int b = i >> 8, k = i & (2 * H - 1);
    yq[i] = (k < H) ? embed[2 * H + k] : q[b * H + (k - H)];
}

// in-place log_softmax over one vocab row per block (float4 vectorized)
__global__ void lsm(float* __restrict__ base, long long rowstride)
{
    float4* row = (float4*)(base + (long long)blockIdx.x * rowstride);
    const int N4 = VOCAB / 4;
    __shared__ float red[256];
    int tid = threadIdx.x;
    float mx = -1e30f;
    for (int i = tid; i < N4; i += 256) {
        float4 v = row[i];
        mx = fmaxf(mx, fmaxf(fmaxf(v.x, v.y), fmaxf(v.z, v.w)));
    }
    red[tid] = mx; __syncthreads();
    for (int o = 128; o > 0; o >>= 1) {
        if (tid < o) red[tid] = fmaxf(red[tid], red[tid + o]);
        __syncthreads();
    }
    mx = red[0]; __syncthreads();
    float s = 0.f;
    for (int i = tid; i < N4; i += 256) {
        float4 v = row[i];
        s += expf(v.x - mx) + expf(v.y - mx) + expf(v.z - mx) + expf(v.w - mx);
    }
    red[tid] = s; __syncthreads();
    for (int o = 128; o > 0; o >>= 1) {
        if (tid < o) red[tid] += red[tid + o];
        __syncthreads();
    }
    float lse = mx + logf(red[0]);
    for (int i = tid; i < N4; i += 256) {
        float4 v = row[i];
        v.x -= lse; v.y -= lse; v.z -= lse; v.w -= lse;
        row[i] = v;
    }
}

// ---------------- host side ----------------
static void* sym_addr(const void* s) { void* p = nullptr; cudaGetSymbolAddress(&p, s); return p; }

static void tgemm(const float* A, const float* emb, const int* idx, int idx_stride, int idx_off,
                  const float* W, const float* bias, float* C, long long ldc,
                  int M, int N, int K)
{
    dim3 grid((N + 127) / 128, (M + 63) / 64);
    tmma_gemm<<<grid, 256>>>(A, emb, idx, idx_stride, idx_off, W, bias, C, ldc, M, N, K);
}

extern "C" void kernel_launch(void* const* d_in, const int* in_sizes, int n_in,
                              void* d_out, int out_size)
{
    const int* facts = (const int*)d_in[0];
    const int* fmask = (const int*)d_in[1];
    const int* ques  = (const int*)d_in[2];
    const int* qmask = (const int*)d_in[3];
    int ai = 4;
    if (in_sizes[4] == 1) ai = 5;
    const float* embed   = (const float*)d_in[ai++];
    const float* ig_Wih  = (const float*)d_in[ai++];
    const float* ig_Whh  = (const float*)d_in[ai++];
    const float* ig_bih  = (const float*)d_in[ai++];
    const float* ig_bhh  = (const float*)d_in[ai++];
    const float* qg_Wih  = (const float*)d_in[ai++];
    const float* qg_Whh  = (const float*)d_in[ai++];
    const float* qg_bih  = (const float*)d_in[ai++];
    const float* qg_bhh  = (const float*)d_in[ai++];
    const float* at_Wih  = (const float*)d_in[ai++];
    const float* at_Whh  = (const float*)d_in[ai++];
    const float* at_bih  = (const float*)d_in[ai++];
    const float* at_bhh  = (const float*)d_in[ai++];
    const float* me_Wih  = (const float*)d_in[ai++];
    const float* me_Whh  = (const float*)d_in[ai++];
    const float* me_bih  = (const float*)d_in[ai++];
    const float* me_bhh  = (const float*)d_in[ai++];
    const float* an_Wih  = (const float*)d_in[ai++];
    const float* an_Whh  = (const float*)d_in[ai++];
    const float* an_bih  = (const float*)d_in[ai++];
    const float* an_bhh  = (const float*)d_in[ai++];
    const float* gate_W1 = (const float*)d_in[ai++];
    const float* gate_b1 = (const float*)d_in[ai++];
    const float* gate_W2 = (const float*)d_in[ai++];
    const float* gate_b2 = (const float*)d_in[ai++];
    const float* fc_W    = (const float*)d_in[ai++];
    const float* fc_b    = (const float*)d_in[ai++];
    float* out = (float*)d_out;
    int TD = out_size / (BATCH * VOCAB);
    if (TD <= 0) TD = 8;

    float* embW = (float*)sym_addr(g_embW);
    float* h    = (float*)sym_addr(g_h);
    float* encf = (float*)sym_addr(g_encf);
    int*   flen = (int*)  sym_addr(g_flen);
    int*   qlen = (int*)  sym_addr(g_qlen);
    float* giq  = (float*)sym_addr(g_giq);
    float* q    = (float*)sym_addr(g_q);
    float* giat = (float*)sym_addr(g_giat);
    float* Z    = (float*)sym_addr(g_Z);
    float* P1   = (float*)sym_addr(g_P1);
    float* P2   = (float*)sym_addr(g_P2);
    float* W1a  = (float*)sym_addr(g_W1a);
    float* W1b  = (float*)sym_addr(g_W1b);
    float* mem  = (float*)sym_addr(g_mem);
    float* e    = (float*)sym_addr(g_e);
    float* yq   = (float*)sym_addr(g_yq);
    float* gian = (float*)sym_addr(g_gian);
    float* hdec = (float*)sym_addr(g_hdec);

    static int attr_done = 0;
    if (!attr_done) {
        cudaFuncSetAttribute(tmma_gru_step, cudaFuncAttributeMaxDynamicSharedMemorySize, 99328);
        cudaFuncSetAttribute(q_encode,      cudaFuncAttributeMaxDynamicSharedMemorySize, 197120);
        cudaFuncSetAttribute(ep_fused,      cudaFuncAttributeMaxDynamicSharedMemorySize, 197120);
        attr_done = 1;
    }

    // ---- sequence lengths ----
    count_len<<<(NSEQ + 255) / 256, 256>>>(fmask, flen, NSEQ, TI);
    count_len<<<1, 128>>>(qmask, qlen, BATCH, TQ);

    // ---- precompute embW = embed @ ig_Wih^T + ig_bih (one big tensor GEMM) ----
    tgemm(embed, nullptr, nullptr, 0, 0, ig_Wih, ig_bih, embW, 3 * H, VOCAB, 3 * H, H);

    // ---- fact encoder: 32 fused tensor-GEMM GRU steps ----
    cudaMemsetAsync(h, 0, (size_t)NSEQ * H * sizeof(float));
    for (int t = 0; t < TI; t++)
        tmma_gru_step<<<NSEQ / 64, 256, 99328>>>(h, ig_Whh, ig_bhh, embW, facts, flen, encf, t);

    // ---- question encoder ----
    tgemm(nullptr, embed, ques, 1, 0, qg_Wih, qg_bih, giq, 3 * H, BATCH * TQ, 3 * H, H);
    q_encode<<<BATCH, H, 197120>>>(giq, qg_Whh, qg_bhh, qlen, q);

    // ---- episodic memory ----
    pack_w1<<<(H * 2 * H) / 256, 256>>>(gate_W1, W1a, W1b);
    tgemm(encf, nullptr, nullptr, 0, 0, at_Wih, at_bih, giat, 3 * H, NSEQ, 3 * H, H);
    build_z<<<(NSEQ * 2 * H) / 256, 256>>>(encf, q, Z);
    tgemm(Z, nullptr, nullptr, 0, 0, W1a, gate_b1, P1, H, NSEQ, H, 2 * H);
    cudaMemcpyAsync(mem, q, (size_t)BATCH * H * sizeof(float), cudaMemcpyDeviceToDevice);

    for (int ep = 0; ep < 3; ep++) {
        build_z<<<(NSEQ * 2 * H) / 256, 256>>>(encf, mem, Z);
        tgemm(Z, nullptr, nullptr, 0, 0, W1b, nullptr, P2, H, NSEQ, H, 2 * H);
        ep_fused<<<BATCH, H, 197120>>>(giat, P1, P2, gate_W2, gate_b2, at_Whh, at_bhh, e);
        gru_full<<<BATCH, H>>>(e, mem, mem, me_Wih, me_Whh, me_bih, me_bhh, H);
    }

    // ---- answer decoder ----
    build_yq<<<(BATCH * 2 * H) / 256, 256>>>(embed, q, yq);
    tgemm(yq, nullptr, nullptr, 0, 0, an_Wih, an_bih, gian, 3 * H, BATCH, 3 * H, 2 * H);
    cudaMemcpyAsync(hdec, mem, (size_t)BATCH * H * sizeof(float), cudaMemcpyDeviceToDevice);
    for (int t = 0; t < TD; t++) {
        rec_step<<<BATCH, H>>>(gian, 3 * H, hdec, an_Whh, an_bhh);
        tgemm(hdec, nullptr, nullptr, 0, 0, fc_W, fc_b,
              out + (long long)t * VOCAB, (long long)TD * VOCAB, BATCH, VOCAB, H);
        lsm<<<BATCH, 256>>>(out + (long long)t * VOCAB, (long long)TD * VOCAB);
    }
}

// round 16
// speedup vs baseline: 3.1393x; 1.6346x over previous
#include <cuda_runtime.h>

#define H      128
#define VOCAB  50000
#define BATCH  128
#define TC     50
#define TI     32
#define TQ     32
#define NSEQ   (BATCH * TC)   // 6400
#define MB     48             // sequences per encoder block
#define NBLK   ((NSEQ + MB - 1) / MB)   // 134
#define WSTR   132            // smem stride (conflict-free: 132 % 32 == 4)
#define TDMAX  32

// ---------------- scratch (device globals) ----------------
__device__ __align__(16) float g_embW[VOCAB * 3 * H];   // embed @ ig_Wih^T + ig_bih
__device__ __align__(16) float g_encf[NSEQ * H];
__device__             int   g_flen[NSEQ];
__device__             int   g_qlen[BATCH];
__device__ __align__(16) float g_giq [BATCH * TQ * 3 * H];
__device__ __align__(16) float g_q   [BATCH * H];
__device__ __align__(16) float g_giat[NSEQ * 3 * H];
__device__ __align__(16) float g_Z   [NSEQ * 2 * H];
__device__ __align__(16) float g_P1  [NSEQ * H];
__device__ __align__(16) float g_P2  [NSEQ * H];
__device__ __align__(16) float g_W1a [H * 2 * H];
__device__ __align__(16) float g_W1b [H * 2 * H];
__device__ __align__(16) float g_mem [BATCH * H];
__device__ __align__(16) float g_e   [BATCH * H];
__device__ __align__(16) float g_yq  [BATCH * 2 * H];
__device__ __align__(16) float g_gian[BATCH * 3 * H];
__device__ __align__(16) float g_hdec[BATCH * H];
__device__ __align__(16) float g_hall[BATCH * TDMAX * H];

__device__ __forceinline__ float sigf(float x) { return 1.f / (1.f + expf(-x)); }

__device__ __forceinline__ float gru_comb(float ir, float iz, float in_,
                                          float hr, float hz, float hn, float h) {
    float r = sigf(ir + hr);
    float z = sigf(iz + hz);
    float n = tanhf(in_ + r * hn);
    return (1.f - z) * n + z * h;
}

__device__ __forceinline__ float tanh_fast(float x) {
    float y; asm("tanh.approx.f32 %0, %1;" : "=f"(y) : "f"(x)); return y;
}
__device__ __forceinline__ float sig_fast(float x) {
    return fmaf(tanh_fast(0.5f * x), 0.5f, 0.5f);
}
__device__ __forceinline__ float gru_comb_fast(float ir, float iz, float in_,
                                               float hr, float hz, float hn, float h) {
    float r = sig_fast(ir + hr);
    float z = sig_fast(iz + hz);
    float n = tanh_fast(fmaf(r, hn, in_));
    return fmaf(z, h - n, n);
}

__device__ __forceinline__ unsigned f2tf32(float f) {
    unsigned r; asm("cvt.rna.tf32.f32 %0, %1;" : "=r"(r) : "f"(f)); return r;
}

__device__ __forceinline__ void mma8(float* c, const unsigned* a, const unsigned* b) {
    asm volatile("mma.sync.aligned.m16n8k8.row.col.f32.tf32.tf32.f32 "
                 "{%0,%1,%2,%3}, {%4,%5,%6,%7}, {%8,%9}, {%0,%1,%2,%3};"
                 : "+f"(c[0]), "+f"(c[1]), "+f"(c[2]), "+f"(c[3])
                 : "r"(a[0]), "r"(a[1]), "r"(a[2]), "r"(a[3]), "r"(b[0]), "r"(b[1]));
}

// ================= persistent fact encoder: all 32 GRU steps in one launch ==========
// 48 seqs/block, 4 warps; warp w owns hidden cols [32w, 32w+32) for ALL 3 gates.
// Whh resident in smem as tf32 (loaded once); h resident in smem across steps.
__global__ __launch_bounds__(128, 1) void fact_encoder(
    const float* __restrict__ Whh, const float* __restrict__ bhh,
    const float* __restrict__ embW, const int* __restrict__ facts,
    const int* __restrict__ lens, float* __restrict__ enc)
{
    extern __shared__ unsigned smp[];
    unsigned* Ws = smp;                                // 384 x WSTR (tf32)
    float* hs = (float*)(smp + 384 * WSTR);            // MB x WSTR (fp32)

    int tid = threadIdx.x, lane = tid & 31, w = tid >> 5;
    int g = lane >> 2, qd = lane & 3;
    int seq0 = blockIdx.x * MB;
    int wcol = w * 32;

    // Whh -> tf32 smem (once)
    for (int i = tid; i < 384 * 32; i += 128) {
        int r = i >> 5, c4 = (i & 31) * 4;
        float4 v = *(const float4*)(Whh + r * H + c4);
        unsigned* d = &Ws[r * WSTR + c4];
        d[0] = f2tf32(v.x); d[1] = f2tf32(v.y); d[2] = f2tf32(v.z); d[3] = f2tf32(v.w);
    }
    for (int i = tid; i < MB * WSTR; i += 128) hs[i] = 0.f;

    // hoist bhh + lens
    float2 bh[3][4];
#pragma unroll
    for (int gt = 0; gt < 3; gt++)
#pragma unroll
        for (int f = 0; f < 4; f++)
            bh[gt][f] = *(const float2*)(bhh + gt * H + wcol + f * 8 + 2 * qd);

    int len6[6];
#pragma unroll
    for (int mf = 0; mf < 3; mf++)
#pragma unroll
        for (int hf = 0; hf < 2; hf++) {
            int seq = seq0 + mf * 16 + g + hf * 8;
            len6[mf * 2 + hf] = (seq < NSEQ) ? lens[seq] : -1;
        }
    __syncthreads();

    for (int t = 0; t < TI; t++) {
        float c[3][12][4];
#pragma unroll
        for (int a = 0; a < 3; a++)
#pragma unroll
            for (int b = 0; b < 12; b++)
#pragma unroll
                for (int d = 0; d < 4; d++) c[a][b][d] = 0.f;

#pragma unroll 4
        for (int kc = 0; kc < H; kc += 8) {
            unsigned a[3][4];
#pragma unroll
            for (int mf = 0; mf < 3; mf++) {
                int rb = mf * 16 + g;
                a[mf][0] = f2tf32(hs[rb * WSTR + kc + qd]);
                a[mf][1] = f2tf32(hs[(rb + 8) * WSTR + kc + qd]);
                a[mf][2] = f2tf32(hs[rb * WSTR + kc + qd + 4]);
                a[mf][3] = f2tf32(hs[(rb + 8) * WSTR + kc + qd + 4]);
            }
#pragma unroll
            for (int nf = 0; nf < 12; nf++) {
                int gt = nf >> 2, f = nf & 3;
                int nrow = gt * H + wcol + f * 8 + g;
                unsigned b[2];
                b[0] = Ws[nrow * WSTR + kc + qd];
                b[1] = Ws[nrow * WSTR + kc + qd + 4];
                mma8(c[0][nf], a[0], b);
                mma8(c[1][nf], a[1], b);
                mma8(c[2][nf], a[2], b);
            }
        }
        __syncthreads();   // all A-reads of hs done before overwrite

#pragma unroll
        for (int mf = 0; mf < 3; mf++) {
#pragma unroll
            for (int hf = 0; hf < 2; hf++) {
                int m = mf * 16 + g + hf * 8;
                int seq = seq0 + m;
                int tok = (seq < NSEQ) ? facts[seq * TI + t] : 0;
                const float* gib = embW + (long long)tok * (3 * H);
                bool cap = (seq < NSEQ) && (t == len6[mf * 2 + hf] - 1);
                int ci = hf * 2;
#pragma unroll
                for (int f = 0; f < 4; f++) {
                    int j = wcol + f * 8 + 2 * qd;
                    float2 gr = *(const float2*)(gib + j);
                    float2 gz = *(const float2*)(gib + H + j);
                    float2 gn = *(const float2*)(gib + 2 * H + j);
                    float2 ho = *(const float2*)(&hs[m * WSTR + j]);
                    float hr0 = c[mf][f][ci]     + bh[0][f].x;
                    float hz0 = c[mf][4 + f][ci] + bh[1][f].x;
                    float hn0 = c[mf][8 + f][ci] + bh[2][f].x;
                    float hr1 = c[mf][f][ci + 1]     + bh[0][f].y;
                    float hz1 = c[mf][4 + f][ci + 1] + bh[1][f].y;
                    float hn1 = c[mf][8 + f][ci + 1] + bh[2][f].y;
                    float2 hv;
                    hv.x = gru_comb_fast(gr.x, gz.x, gn.x, hr0, hz0, hn0, ho.x);
                    hv.y = gru_comb_fast(gr.y, gz.y, gn.y, hr1, hz1, hn1, ho.y);
                    *(float2*)(&hs[m * WSTR + j]) = hv;
                    if (cap) *(float2*)(enc + (long long)seq * H + j) = hv;
                }
            }
        }
        __syncthreads();
    }
}

// ---------------- generic tf32 tensor GEMM: C[M,N] = A[M,K] @ W[N,K]^T + bias ----------
__global__ __launch_bounds__(256) void tmma_gemm(
    const float* __restrict__ A, const float* __restrict__ emb,
    const int* __restrict__ idx, int idx_stride, int idx_off,
    const float* __restrict__ W, const float* __restrict__ bias,
    float* __restrict__ C, long long ldc, int M, int N, int K)
{
    __shared__ unsigned As[64 * 36];
    __shared__ unsigned Ws[128 * 36];
    int tid = threadIdx.x, lane = tid & 31, wid = tid >> 5;
    int wm = wid & 1, wn = wid >> 1;
    int g = lane >> 2, qd = lane & 3;
    int m0 = blockIdx.y * 64, n0 = blockIdx.x * 128;

    int ar = tid >> 2, ac = (tid & 3) * 8;
    bool a_ok = (m0 + ar) < M;
    const float* Arow;
    if (idx) {
        int tok = a_ok ? idx[(m0 + ar) * idx_stride + idx_off] : 0;
        Arow = emb + (long long)tok * K;
    } else {
        Arow = A + (long long)(m0 + ar) * K;
    }

    float c[2][4][4] = {};

    for (int kc = 0; kc < K; kc += 32) {
        {
            float4 v0 = a_ok ? *(const float4*)(Arow + kc + ac) : make_float4(0, 0, 0, 0);
            float4 v1 = a_ok ? *(const float4*)(Arow + kc + ac + 4) : make_float4(0, 0, 0, 0);
            unsigned* d = &As[ar * 36 + ac];
            d[0] = f2tf32(v0.x); d[1] = f2tf32(v0.y); d[2] = f2tf32(v0.z); d[3] = f2tf32(v0.w);
            d[4] = f2tf32(v1.x); d[5] = f2tf32(v1.y); d[6] = f2tf32(v1.z); d[7] = f2tf32(v1.w);
        }
        for (int i = tid; i < 1024; i += 256) {
            int r = i >> 3, cc = (i & 7) * 4;
            bool ok = (n0 + r) < N;
            float4 v = ok ? *(const float4*)(W + (long long)(n0 + r) * K + kc + cc)
                          : make_float4(0, 0, 0, 0);
            unsigned* d = &Ws[r * 36 + cc];
            d[0] = f2tf32(v.x); d[1] = f2tf32(v.y); d[2] = f2tf32(v.z); d[3] = f2tf32(v.w);
        }
        __syncthreads();
#pragma unroll
        for (int ks = 0; ks < 4; ks++) {
            int k = ks * 8;
            unsigned a[2][4], b[4][2];
#pragma unroll
            for (int mf = 0; mf < 2; mf++) {
                int rb = wm * 32 + mf * 16 + g;
                a[mf][0] = As[rb * 36 + k + qd];
                a[mf][1] = As[(rb + 8) * 36 + k + qd];
                a[mf][2] = As[rb * 36 + k + qd + 4];
                a[mf][3] = As[(rb + 8) * 36 + k + qd + 4];
            }
#pragma unroll
            for (int nf = 0; nf < 4; nf++) {
                int nb = wn * 32 + nf * 8 + g;
                b[nf][0] = Ws[nb * 36 + k + qd];
                b[nf][1] = Ws[nb * 36 + k + qd + 4];
            }
#pragma unroll
            for (int mf = 0; mf < 2; mf++)
#pragma unroll
                for (int nf = 0; nf < 4; nf++)
                    mma8(c[mf][nf], a[mf], b[nf]);
        }
        __syncthreads();
    }

#pragma unroll
    for (int mf = 0; mf < 2; mf++) {
#pragma unroll
        for (int nf = 0; nf < 4; nf++) {
            int row = m0 + wm * 32 + mf * 16 + g;
            int col = n0 + wn * 32 + nf * 8 + 2 * qd;
            float b0 = 0.f, b1 = 0.f;
            if (bias) { if (col < N) b0 = bias[col]; if (col + 1 < N) b1 = bias[col + 1]; }
            if (row < M) {
                if (col < N)     C[(long long)row * ldc + col]     = c[mf][nf][0] + b0;
                if (col + 1 < N) C[(long long)row * ldc + col + 1] = c[mf][nf][1] + b1;
            }
            if (row + 8 < M) {
                if (col < N)     C[(long long)(row + 8) * ldc + col]     = c[mf][nf][2] + b0;
                if (col + 1 < N) C[(long long)(row + 8) * ldc + col + 1] = c[mf][nf][3] + b1;
            }
        }
    }
}

// ---------------- fused question encoder ----------------
__global__ __launch_bounds__(128) void q_encode(
    const float* __restrict__ gi_all, const float* __restrict__ Whh,
    const float* __restrict__ bhh, const int* __restrict__ qlen,
    float* __restrict__ q)
{
    extern __shared__ float WsT[];   // [k*385 + n]
    __shared__ float hs[H];
    int b = blockIdx.x, j = threadIdx.x;
    for (int s = j; s < 3 * H * H; s += H) {
        int n = s >> 7, k = s & (H - 1);
        WsT[k * 385 + n] = Whh[s];
    }
    float br = bhh[j], bz = bhh[H + j], bn = bhh[2 * H + j];
    hs[j] = 0.f;
    __syncthreads();
    int L = qlen[b];
    for (int t = 0; t < TQ; t++) {
        float hr = br, hz = bz, hn = bn;
#pragma unroll 4
        for (int k = 0; k < H; k++) {
            float hv = hs[k];
            hr += WsT[k * 385 + j] * hv;
            hz += WsT[k * 385 + H + j] * hv;
            hn += WsT[k * 385 + 2 * H + j] * hv;
        }
        const float* gi = gi_all + (long long)(b * TQ + t) * (3 * H);
        float hnew = gru_comb(gi[j], gi[H + j], gi[2 * H + j], hr, hz, hn, hs[j]);
        __syncthreads();
        hs[j] = hnew;
        __syncthreads();
        if (t == L - 1) q[b * H + j] = hnew;
    }
}

// ---------------- fused episode ----------------
__global__ __launch_bounds__(128) void ep_fused(
    const float* __restrict__ giat, const float* __restrict__ P1,
    const float* __restrict__ P2, const float* __restrict__ W2,
    const float* __restrict__ b2, const float* __restrict__ Whh,
    const float* __restrict__ bhh, float* __restrict__ e_out)
{
    extern __shared__ float WsT[];
    __shared__ float hs[H];
    __shared__ float wsum[4];
    int b = blockIdx.x, j = threadIdx.x;
    int lane = j & 31, wrp = j >> 5;
    for (int s = j; s < 3 * H * H; s += H) {
        int n = s >> 7, k = s & (H - 1);
        WsT[k * 385 + n] = Whh[s];
    }
    float br = bhh[j], bz = bhh[H + j], bn = bhh[2 * H + j];
    float w2j = W2[j], b2v = b2[0];
    hs[j] = 0.f;
    float en = 0.f;
    __syncthreads();
    for (int t = 0; t < TC; t++) {
        long long s = (long long)(b * TC + t);
        float u = tanhf(P1[s * H + j] + P2[s * H + j]) * w2j;
        for (int o = 16; o; o >>= 1) u += __shfl_down_sync(0xffffffffu, u, o);
        if (lane == 0) wsum[wrp] = u;
        float hr = br, hz = bz, hn = bn;
#pragma unroll 4
        for (int k = 0; k < H; k++) {
            float hv = hs[k];
            hr += WsT[k * 385 + j] * hv;
            hz += WsT[k * 385 + H + j] * hv;
            hn += WsT[k * 385 + 2 * H + j] * hv;
        }
        __syncthreads();
        float gate = sigf(wsum[0] + wsum[1] + wsum[2] + wsum[3] + b2v);
        const float* gi = giat + s * (3 * H);
        float h2 = gru_comb(gi[j], gi[H + j], gi[2 * H + j], hr, hz, hn, hs[j]);
        en = gate * h2 + (1.f - gate) * hs[j];
        __syncthreads();
        hs[j] = en;
        __syncthreads();
    }
    e_out[b * H + j] = en;
}

// ---------------- decoder recurrent step (writes hidden + scattered copy) ----------
__global__ void rec_step(const float* __restrict__ gi, int gstride,
                         float* __restrict__ h,
                         const float* __restrict__ Whh, const float* __restrict__ bhh,
                         float* __restrict__ hall, int TD, int t)
{
    __shared__ __align__(16) float hs[H];
    int b = blockIdx.x, j = threadIdx.x;
    hs[j] = h[b * H + j];
    __syncthreads();
    float hr = bhh[j], hz = bhh[H + j], hn = bhh[2 * H + j];
    const float4* wr = (const float4*)(Whh + j * H);
    const float4* wz = (const float4*)(Whh + (H + j) * H);
    const float4* wn = (const float4*)(Whh + (2 * H + j) * H);
    const float4* h4 = (const float4*)hs;
#pragma unroll 8
    for (int k = 0; k < H / 4; k++) {
        float4 hv = h4[k];
        float4 a = wr[k]; hr += hv.x * a.x + hv.y * a.y + hv.z * a.z + hv.w * a.w;
        float4 c = wz[k]; hz += hv.x * c.x + hv.y * c.y + hv.z * c.z + hv.w * c.w;
        float4 d = wn[k]; hn += hv.x * d.x + hv.y * d.y + hv.z * d.z + hv.w * d.w;
    }
    const float* g = gi + (long long)b * gstride;
    float hnew = gru_comb(g[j], g[H + j], g[2 * H + j], hr, hz, hn, hs[j]);
    h[b * H + j] = hnew;
    hall[(long long)(b * TD + t) * H + j] = hnew;
}

// ---------------- memory-update GRU ----------------
__global__ void gru_full(const float* __restrict__ x, const float* __restrict__ h_in,
                         float* __restrict__ h_out,
                         const float* __restrict__ Wih, const float* __restrict__ Whh,
                         const float* __restrict__ bih, const float* __restrict__ bhh,
                         int IN)
{
    __shared__ __align__(16) float xs[2 * H];
    __shared__ __align__(16) float hs[H];
    int b = blockIdx.x, j = threadIdx.x;
    hs[j] = h_in[b * H + j];
    for (int k = j; k < IN; k += H) xs[k] = x[b * IN + k];
    __syncthreads();
    float ir = bih[j], iz = bih[H + j], in_ = bih[2 * H + j];
    const float4* xr = (const float4*)(Wih + (long long)j * IN);
    const float4* xz = (const float4*)(Wih + (long long)(H + j) * IN);
    const float4* xn = (const float4*)(Wih + (long long)(2 * H + j) * IN);
    const float4* x4 = (const float4*)xs;
    for (int k = 0; k < IN / 4; k++) {
        float4 xv = x4[k];
        float4 a = xr[k]; ir += xv.x * a.x + xv.y * a.y + xv.z * a.z + xv.w * a.w;
        float4 c = xz[k]; iz += xv.x * c.x + xv.y * c.y + xv.z * c.z + xv.w * c.w;
        float4 d = xn[k]; in_ += xv.x * d.x + xv.y * d.y + xv.z * d.z + xv.w * d.w;
    }
    float hr = bhh[j], hz = bhh[H + j], hn = bhh[2 * H + j];
    const float4* wr = (const float4*)(Whh + j * H);
    const float4* wz = (const float4*)(Whh + (H + j) * H);
    const float4* wn = (const float4*)(Whh + (2 * H + j) * H);
    const float4* h4 = (const float4*)hs;
#pragma unroll 8
    for (int k = 0; k < H / 4; k++) {
        float4 hv = h4[k];
        float4 a = wr[k]; hr += hv.x * a.x + hv.y * a.y + hv.z * a.z + hv.w * a.w;
        float4 c = wz[k]; hz += hv.x * c.x + hv.y * c.y + hv.z * c.z + hv.w * c.w;
        float4 d = wn[k]; hn += hv.x * d.x + hv.y * d.y + hv.z * d.z + hv.w * d.w;
    }
    h_out[b * H + j] = gru_comb(ir, iz, in_, hr, hz, hn, hs[j]);
}

// ---------------- misc small kernels ----------------
__global__ void count_len(const int* __restrict__ masks, int* __restrict__ lens, int n, int T)
{
    int i = blockIdx.x * blockDim.x + threadIdx.x;
    if (i < n) {
        int c = 0;
        for (int t = 0; t < T; t++) c += (masks[i * T + t] == 0);
        lens[i] = c;
    }
}

__global__ void build_z(const float* __restrict__ encf, const float* __restrict__ vec,
                        float* __restrict__ Z)
{
    int i = blockIdx.x * blockDim.x + threadIdx.x;
    if (i >= NSEQ * 2 * H) return;
    int s = i >> 8, k = i & (2 * H - 1);
    int b = s / TC;
    int kk = k & (H - 1);
    float f = encf[s * H + kk], v = vec[b * H + kk];
    Z[i] = (k < H) ? f * v : fabsf(f - v);
}

__global__ void pack_w1(const float* __restrict__ W1, float* __restrict__ Wa,
                        float* __restrict__ Wb)
{
    int i = blockIdx.x * blockDim.x + threadIdx.x;
    if (i >= H * 2 * H) return;
    int j = i >> 8, k = i & (2 * H - 1);
    int ca = (k < H) ? k : (k + H);
    int cb = (k < H) ? (k + H) : (k + 2 * H);
    Wa[i] = W1[j * 4 * H + ca];
    Wb[i] = W1[j * 4 * H + cb];
}

__global__ void build_yq(const float* __restrict__ embed, const float* __restrict__ q,
                         float* __restrict__ yq)
{
    int i = blockIdx.x * blockDim.x + threadIdx.x;
    if (i >= BATCH * 2 * H) return;
    int b = i >> 8, k = i & (2 * H - 1);
    yq[i] = (k < H) ? embed[2 * H + k] : q[b * H + (k - H)];
}

// in-place log_softmax, one vocab row per block
__global__ void lsm(float* __restrict__ base, long long rowstride)
{
    float4* row = (float4*)(base + (long long)blockIdx.x * rowstride);
    const int N4 = VOCAB / 4;
    __shared__ float red[256];
    int tid = threadIdx.x;
    float mx = -1e30f;
    for (int i = tid; i < N4; i += 256) {
        float4 v = row[i];
        mx = fmaxf(mx, fmaxf(fmaxf(v.x, v.y), fmaxf(v.z, v.w)));
    }
    red[tid] = mx; __syncthreads();
    for (int o = 128; o > 0; o >>= 1) {
        if (tid < o) red[tid] = fmaxf(red[tid], red[tid + o]);
        __syncthreads();
    }
    mx = red[0]; __syncthreads();
    float s = 0.f;
    for (int i = tid; i < N4; i += 256) {
        float4 v = row[i];
        s += __expf(v.x - mx) + __expf(v.y - mx) + __expf(v.z - mx) + __expf(v.w - mx);
    }
    red[tid] = s; __syncthreads();
    for (int o = 128; o > 0; o >>= 1) {
        if (tid < o) red[tid] += red[tid + o];
        __syncthreads();
    }
    float lse = mx + logf(red[0]);
    for (int i = tid; i < N4; i += 256) {
        float4 v = row[i];
        v.x -= lse; v.y -= lse; v.z -= lse; v.w -= lse;
        row[i] = v;
    }
}

// ---------------- host side ----------------
static void* sym_addr(const void* s) { void* p = nullptr; cudaGetSymbolAddress(&p, s); return p; }

static void tgemm(const float* A, const float* emb, const int* idx, int idx_stride, int idx_off,
                  const float* W, const float* bias, float* C, long long ldc,
                  int M, int N, int K)
{
    dim3 grid((N + 127) / 128, (M + 63) / 64);
    tmma_gemm<<<grid, 256>>>(A, emb, idx, idx_stride, idx_off, W, bias, C, ldc, M, N, K);
}

extern "C" void kernel_launch(void* const* d_in, const int* in_sizes, int n_in,
                              void* d_out, int out_size)
{
    const int* facts = (const int*)d_in[0];
    const int* fmask = (const int*)d_in[1];
    const int* ques  = (const int*)d_in[2];
    const int* qmask = (const int*)d_in[3];
    int ai = 4;
    if (in_sizes[4] == 1) ai = 5;
    const float* embed   = (const float*)d_in[ai++];
    const float* ig_Wih  = (const float*)d_in[ai++];
    const float* ig_Whh  = (const float*)d_in[ai++];
    const float* ig_bih  = (const float*)d_in[ai++];
    const float* ig_bhh  = (const float*)d_in[ai++];
    const float* qg_Wih  = (const float*)d_in[ai++];
    const float* qg_Whh  = (const float*)d_in[ai++];
    const float* qg_bih  = (const float*)d_in[ai++];
    const float* qg_bhh  = (const float*)d_in[ai++];
    const float* at_Wih  = (const float*)d_in[ai++];
    const float* at_Whh  = (const float*)d_in[ai++];
    const float* at_bih  = (const float*)d_in[ai++];
    const float* at_bhh  = (const float*)d_in[ai++];
    const float* me_Wih  = (const float*)d_in[ai++];
    const float* me_Whh  = (const float*)d_in[ai++];
    const float* me_bih  = (const float*)d_in[ai++];
    const float* me_bhh  = (const float*)d_in[ai++];
    const float* an_Wih  = (const float*)d_in[ai++];
    const float* an_Whh  = (const float*)d_in[ai++];
    const float* an_bih  = (const float*)d_in[ai++];
    const float* an_bhh  = (const float*)d_in[ai++];
    const float* gate_W1 = (const float*)d_in[ai++];
    const float* gate_b1 = (const float*)d_in[ai++];
    const float* gate_W2 = (const float*)d_in[ai++];
    const float* gate_b2 = (const float*)d_in[ai++];
    const float* fc_W    = (const float*)d_in[ai++];
    const float* fc_b    = (const float*)d_in[ai++];
    float* out = (float*)d_out;
    int TD = out_size / (BATCH * VOCAB);
    if (TD <= 0) TD = 8;
    if (TD > TDMAX) TD = TDMAX;

    float* embW = (float*)sym_addr(g_embW);
    float* encf = (float*)sym_addr(g_encf);
    int*   flen = (int*)  sym_addr(g_flen);
    int*   qlen = (int*)  sym_addr(g_qlen);
    float* giq  = (float*)sym_addr(g_giq);
    float* q    = (float*)sym_addr(g_q);
    float* giat = (float*)sym_addr(g_giat);
    float* Z    = (float*)sym_addr(g_Z);
    float* P1   = (float*)sym_addr(g_P1);
    float* P2   = (float*)sym_addr(g_P2);
    float* W1a  = (float*)sym_addr(g_W1a);
    float* W1b  = (float*)sym_addr(g_W1b);
    float* mem  = (float*)sym_addr(g_mem);
    float* e    = (float*)sym_addr(g_e);
    float* yq   = (float*)sym_addr(g_yq);
    float* gian = (float*)sym_addr(g_gian);
    float* hdec = (float*)sym_addr(g_hdec);
    float* hall = (float*)sym_addr(g_hall);

    static int attr_done = 0;
    if (!attr_done) {
        cudaFuncSetAttribute(fact_encoder, cudaFuncAttributeMaxDynamicSharedMemorySize,
                             (384 + MB) * WSTR * 4);
        cudaFuncSetAttribute(q_encode, cudaFuncAttributeMaxDynamicSharedMemorySize, 197120);
        cudaFuncSetAttribute(ep_fused, cudaFuncAttributeMaxDynamicSharedMemorySize, 197120);
        attr_done = 1;
    }

    // ---- sequence lengths ----
    count_len<<<(NSEQ + 255) / 256, 256>>>(fmask, flen, NSEQ, TI);
    count_len<<<1, 128>>>(qmask, qlen, BATCH, TQ);

    // ---- precompute embW = embed @ ig_Wih^T + ig_bih ----
    tgemm(embed, nullptr, nullptr, 0, 0, ig_Wih, ig_bih, embW, 3 * H, VOCAB, 3 * H, H);

    // ---- fact encoder: ONE persistent launch, all 32 steps ----
    fact_encoder<<<NBLK, 128, (384 + MB) * WSTR * 4>>>(ig_Whh, ig_bhh, embW, facts, flen, encf);

    // ---- question encoder ----
    tgemm(nullptr, embed, ques, 1, 0, qg_Wih, qg_bih, giq, 3 * H, BATCH * TQ, 3 * H, H);
    q_encode<<<BATCH, H, 197120>>>(giq, qg_Whh, qg_bhh, qlen, q);

    // ---- episodic memory ----
    pack_w1<<<(H * 2 * H) / 256, 256>>>(gate_W1, W1a, W1b);
    tgemm(encf, nullptr, nullptr, 0, 0, at_Wih, at_bih, giat, 3 * H, NSEQ, 3 * H, H);
    build_z<<<(NSEQ * 2 * H) / 256, 256>>>(encf, q, Z);
    tgemm(Z, nullptr, nullptr, 0, 0, W1a, gate_b1, P1, H, NSEQ, H, 2 * H);
    cudaMemcpyAsync(mem, q, (size_t)BATCH * H * sizeof(float), cudaMemcpyDeviceToDevice);

    for (int ep = 0; ep < 3; ep++) {
        build_z<<<(NSEQ * 2 * H) / 256, 256>>>(encf, mem, Z);
        tgemm(Z, nullptr, nullptr, 0, 0, W1b, nullptr, P2, H, NSEQ, H, 2 * H);
        ep_fused<<<BATCH, H, 197120>>>(giat, P1, P2, gate_W2, gate_b2, at_Whh, at_bhh, e);
        gru_full<<<BATCH, H>>>(e, mem, mem, me_Wih, me_Whh, me_bih, me_bhh, H);
    }

    // ---- answer decoder: 8 tiny recurrent steps, then ONE vocab GEMM + ONE lsm ----
    build_yq<<<(BATCH * 2 * H) / 256, 256>>>(embed, q, yq);
    tgemm(yq, nullptr, nullptr, 0, 0, an_Wih, an_bih, gian, 3 * H, BATCH, 3 * H, 2 * H);
    cudaMemcpyAsync(hdec, mem, (size_t)BATCH * H * sizeof(float), cudaMemcpyDeviceToDevice);
    for (int t = 0; t < TD; t++)
        rec_step<<<BATCH, H>>>(gian, 3 * H, hdec, an_Whh, an_bhh, hall, TD, t);
    tgemm(hall, nullptr, nullptr, 0, 0, fc_W, fc_b, out, VOCAB, BATCH * TD, VOCAB, H);
    lsm<<<BATCH * TD, 256>>>(out, VOCAB);
}